// round 14
// baseline (speedup 1.0000x reference)
#include <cuda_runtime.h>
#include <math.h>

#define NN 50000
#define NE 400000
#define NCELL 64
#define NB 512
#define EPB_S ((NE + NB - 1) / NB)
#define CHUNKS 50
#define EBLK 128
#define EPAD 1024

typedef unsigned long long ull;

// ---- persistent scratch (no allocations allowed) ----
__device__ float  g_h0[NN * 16];
__device__ float  g_h1[NN * 16];
__device__ float  g_accA[NN * 16];
__device__ float  g_accB[NN * 16];
__device__ int    g_hist[NCELL];
__device__ int    g_segs[NCELL + 1];
__device__ int    g_bcount[NCELL * NB];
// zero-initialized; pad tail [NE, NE+EPAD) is never written -> stays zero across
// replays, making unguarded prefetch loads safe (srcdst=0 -> reads h[0]).
__device__ float4 g_e4[NE + EPAD];   // {srcdst packed 16/16 (bitcast), fx, fy, fz}

// ---- f32x2 packed-math helpers ----
__device__ __forceinline__ ull pack2(float lo, float hi) {
    ull r;
    asm("mov.b64 %0, {%1, %2};" : "=l"(r) : "f"(lo), "f"(hi));
    return r;
}
__device__ __forceinline__ void unpack2(ull v, float& lo, float& hi) {
    asm("mov.b64 {%0, %1}, %2;" : "=f"(lo), "=f"(hi) : "l"(v));
}
__device__ __forceinline__ void ffma2(ull& d, ull a, ull b) {
    asm("fma.rn.f32x2 %0, %1, %2, %0;" : "+l"(d) : "l"(a), "l"(b));
}
__device__ __forceinline__ ull add2(ull a, ull b) {
    ull r;
    asm("add.rn.f32x2 %0, %1, %2;" : "=l"(r) : "l"(a), "l"(b));
    return r;
}

__device__ __forceinline__ void cell_frac(float a, int& k0, float& fr) {
    float p = fminf(fmaxf(a, 0.f), 1.f) * 4.f;   // KSIZE-1 = 4
    int k = (int)floorf(p);
    k = k > 3 ? 3 : k;
    k0 = k;
    fr = p - (float)k;
}

// ---- pass 1: per-block cell histogram ----
__global__ __launch_bounds__(256)
void k_hist(const float* __restrict__ ea) {
    __shared__ int sh[NCELL];
    if (threadIdx.x < NCELL) sh[threadIdx.x] = 0;
    __syncthreads();
    int b = blockIdx.x;
    int e0 = b * EPB_S, e1 = min(NE, e0 + EPB_S);
    for (int e = e0 + threadIdx.x; e < e1; e += 256) {
        int kx, ky, kz; float f;
        cell_frac(ea[e * 3 + 0], kx, f);
        cell_frac(ea[e * 3 + 1], ky, f);
        cell_frac(ea[e * 3 + 2], kz, f);
        atomicAdd(&sh[kx * 16 + ky * 4 + kz], 1);
    }
    __syncthreads();
    if (threadIdx.x < NCELL) g_bcount[threadIdx.x * NB + b] = sh[threadIdx.x];
}

// ---- pass 2: per-cell exclusive scan over blocks ----
__global__ __launch_bounds__(NB)
void k_cellscan() {
    __shared__ int sh[NB];
    int c = blockIdx.x, t = threadIdx.x;
    int v = g_bcount[c * NB + t];
    sh[t] = v;
    __syncthreads();
    for (int off = 1; off < NB; off <<= 1) {
        int val = (t >= off) ? sh[t - off] : 0;
        __syncthreads();
        sh[t] += val;
        __syncthreads();
    }
    g_bcount[c * NB + t] = sh[t] - v;
    if (t == NB - 1) g_hist[c] = sh[t];
}

// ---- pass 3: serial scan over 64 cells ----
__global__ void k_scan() {
    int c = threadIdx.x;
    if (c < NCELL) {
        int s = 0;
        for (int j = 0; j < c; j++) s += g_hist[j];
        g_segs[c] = s;
        if (c == NCELL - 1) g_segs[NCELL] = s + g_hist[c];
    }
}

// ---- pass 4: scatter with shared-memory cursors; src+dst packed 16/16 ----
__global__ __launch_bounds__(256)
void k_scatter(const float* __restrict__ ea, const int* __restrict__ ei) {
    __shared__ int cur[NCELL];
    int b = blockIdx.x;
    if (threadIdx.x < NCELL)
        cur[threadIdx.x] = g_segs[threadIdx.x] + g_bcount[threadIdx.x * NB + b];
    __syncthreads();
    int e0 = b * EPB_S, e1 = min(NE, e0 + EPB_S);
    for (int e = e0 + threadIdx.x; e < e1; e += 256) {
        int kx, ky, kz; float fx, fy, fz;
        cell_frac(ea[e * 3 + 0], kx, fx);
        cell_frac(ea[e * 3 + 1], ky, fy);
        cell_frac(ea[e * 3 + 2], kz, fz);
        int cell = kx * 16 + ky * 4 + kz;
        int pos = atomicAdd(&cur[cell], 1);
        unsigned int sd = (unsigned int)ei[e] | ((unsigned int)ei[NE + e] << 16);
        float4 v;
        v.x = __uint_as_float(sd);
        v.y = fx; v.z = fy; v.w = fz;
        g_e4[pos] = v;
    }
}

// ---- first layer prologue ----
__global__ void k_first(const float* __restrict__ x, const float* __restrict__ root,
                        const float* __restrict__ bias, float* __restrict__ h,
                        float* __restrict__ acc) {
    int idx = blockIdx.x * blockDim.x + threadIdx.x;
    if (idx >= NN * 8) return;
    int n = idx >> 3, o = idx & 7;
    const float L = -0.22703196f, U = 0.36853024f;
    float t = (x[n] - L) / (U - L) * 20.f - 10.f;
    t = fminf(fmaxf(t, -10.f), 10.f);
    if (o == 0) h[n] = t;
    acc[idx] = bias[o] + t * root[o];
}

// ---- fused layer boundary: h = elu(accin); accout = bias + h @ root ----
template <int CIN, int COUT>
__global__ __launch_bounds__(256)
void k_act(const float* __restrict__ accin, float* __restrict__ hout,
           const float* __restrict__ root, const float* __restrict__ bias,
           float* __restrict__ accout) {
    __shared__ float sh[16 * CIN];
    __shared__ float sr[CIN * COUT];
    int t = threadIdx.x;
    int n0 = blockIdx.x * 16;
    if (t < CIN * COUT) sr[t] = root[t];
    if (t < 16 * CIN) {
        int n = n0 + t / CIN;
        float v = accin[n * CIN + (t % CIN)];
        v = v > 0.f ? v : expm1f(v);
        sh[t] = v;
        hout[n * CIN + (t % CIN)] = v;
    }
    __syncthreads();
    if (t < 16 * COUT) {
        int nl = t / COUT, o = t % COUT;
        float s = bias[o];
#pragma unroll
        for (int i = 0; i < CIN; i++) s += sh[nl * CIN + i] * sr[i * COUT + o];
        accout[(n0 + nl) * COUT + o] = s;
    }
}

__global__ void k_elu(const float* __restrict__ a, float* __restrict__ o, int n) {
    int i = blockIdx.x * blockDim.x + threadIdx.x;
    if (i < n) {
        float v = a[i];
        o[i] = v > 0.f ? v : expm1f(v);
    }
}

// ---- edge kernel, CIN==1 (layer 1): ping-pong depth-2, unguarded pad prefetch ----
__global__ __launch_bounds__(EBLK)
void k_edge1(const float* __restrict__ xin, const float* __restrict__ w,
             float* __restrict__ acc) {
    constexpr int COUT = 8, G = 16, EPB = EBLK / G;
    constexpr int STEP = CHUNKS * EPB;
    int cell = blockIdx.x / CHUNKS;
    int chunk = blockIdx.x % CHUNKS;
    int tid = threadIdx.x;
    int g = tid % G;
    int o = g % COUT;
    int h = g / COUT;
    int eslot = tid / G;
    int lane = tid & 31;
    unsigned gmask = ((1u << G) - 1u) << ((lane / G) * G);

    int cx = cell >> 4, cy = (cell >> 2) & 3, cz = cell & 3;
    float wr[4];
#pragma unroll
    for (int sl = 0; sl < 4; sl++) {
        int bx = sl & 1, by = (sl >> 1) & 1;
        int k = (cx + bx) * 25 + (cy + by) * 5 + (cz + h);
        wr[sl] = w[k * COUT + o];
    }

    int e1 = g_segs[cell + 1];
    int e = g_segs[cell] + chunk * EPB + eslot;
    if (e >= e1) return;

    auto compute = [&](const float4& v, float x) {
        float fx = v.y, fy = v.z, fz = v.w;
        float wz = h ? fz : (1.f - fz);
        float gx = 1.f - fx, gy = 1.f - fy;
        float s = (gx * gy) * wr[0] + (fx * gy) * wr[1]
                + (gx * fy) * wr[2] + (fx * fy) * wr[3];
        float av = x * (s * wz);
        av += __shfl_xor_sync(gmask, av, COUT);
        float hi2 = __shfl_xor_sync(gmask, av, 1);
        unsigned dst = ((unsigned)__float_as_int(v.x)) >> 16;
        if (h == 0 && (o & 1) == 0)
            asm volatile("red.global.add.v2.f32 [%0], {%1, %2};"
                         :: "l"(acc + dst * COUT + o), "f"(av), "f"(hi2) : "memory");
    };

    // invariant before A: vA ~ e, vB ~ e+S, xA = x(vA)
    float4 vA = g_e4[e];
    float4 vB = g_e4[e + STEP];             // pad-safe
    float xA = xin[__float_as_int(vA.x) & 0xffff];
    float xB;

    while (true) {
        // A: consume (vA, xA)
        xB = xin[__float_as_int(vB.x) & 0xffff];
        compute(vA, xA);
        vA = g_e4[e + 2 * STEP];            // pad-safe; now vA ~ e+2S
        e += STEP;
        if (e >= e1) break;
        // B: consume (vB, xB); vA ~ e+S now
        xA = xin[__float_as_int(vA.x) & 0xffff];
        compute(vB, xB);
        vB = g_e4[e + 2 * STEP];            // pad-safe; now vB ~ e+2S
        e += STEP;
        if (e >= e1) break;
    }
}

// ---- edge kernel, packed f32x2, ping-pong depth-2, pad prefetch (CIN {8,16}) ----
template <int CIN>
__device__ __forceinline__ void edge_loadx(ull* xp, const float* __restrict__ xin,
                                           float vx) {
    constexpr int P = CIN / 2;
    const longlong2* xv = reinterpret_cast<const longlong2*>(
        xin + (__float_as_int(vx) & 0xffff) * CIN);
#pragma unroll
    for (int i = 0; i < P / 2; i++) {
        longlong2 q = xv[i];
        xp[2 * i] = (ull)q.x;
        xp[2 * i + 1] = (ull)q.y;
    }
}

template <int CIN, int COUT>
__global__ __launch_bounds__(EBLK)
void k_edgeP(const float* __restrict__ xin, const float* __restrict__ w,
             float* __restrict__ acc) {
    constexpr int G = 2 * COUT;
    constexpr int EPB = EBLK / G;
    constexpr int STEP = CHUNKS * EPB;
    constexpr int P = CIN / 2;
    int cell = blockIdx.x / CHUNKS;
    int chunk = blockIdx.x % CHUNKS;
    int tid = threadIdx.x;
    int g = tid % G;
    int o = g % COUT;
    int h = g / COUT;
    int eslot = tid / G;
    int lane = tid & 31;
    unsigned gmask = (G >= 32) ? 0xffffffffu : (((1u << G) - 1u) << ((lane / G) * G));

    int cx = cell >> 4, cy = (cell >> 2) & 3, cz = cell & 3;

    ull wp[4][P];
#pragma unroll
    for (int sl = 0; sl < 4; sl++) {
        int bx = sl & 1, by = (sl >> 1) & 1;
        int k = (cx + bx) * 25 + (cy + by) * 5 + (cz + h);
#pragma unroll
        for (int i = 0; i < P; i++)
            wp[sl][i] = pack2(w[(k * CIN + 2 * i) * COUT + o],
                              w[(k * CIN + 2 * i + 1) * COUT + o]);
    }

    int e1 = g_segs[cell + 1];
    int e = g_segs[cell] + chunk * EPB + eslot;
    if (e >= e1) return;

    auto compute = [&](const float4& v, const ull* xp) {
        float fx = v.y, fy = v.z, fz = v.w;
        float wz = h ? fz : (1.f - fz);
        float gx = 1.f - fx, gy = 1.f - fy;
        float bas[4];
        bas[0] = gx * gy * wz; bas[1] = fx * gy * wz;
        bas[2] = gx * fy * wz; bas[3] = fx * fy * wz;

        ull av2 = 0;
#pragma unroll
        for (int sl = 0; sl < 4; sl++) {
            ull t0 = 0, t1 = 0;
#pragma unroll
            for (int i = 0; i + 1 < P; i += 2) {
                ffma2(t0, xp[i], wp[sl][i]);
                ffma2(t1, xp[i + 1], wp[sl][i + 1]);
            }
            if constexpr (P & 1) ffma2(t0, xp[P - 1], wp[sl][P - 1]);
            ffma2(av2, pack2(bas[sl], bas[sl]), add2(t0, t1));
        }
        float alo, ahi;
        unpack2(av2, alo, ahi);
        float av = alo + ahi;

        av += __shfl_xor_sync(gmask, av, COUT);   // combine z-corner halves
        unsigned dst = ((unsigned)__float_as_int(v.x)) >> 16;
        if constexpr (COUT >= 8) {
            float hi2 = __shfl_xor_sync(gmask, av, 1);
            if (h == 0 && (o & 1) == 0)
                asm volatile("red.global.add.v2.f32 [%0], {%1, %2};"
                             :: "l"(acc + dst * COUT + o), "f"(av), "f"(hi2) : "memory");
        } else {
            if (h == 0) atomicAdd(acc + dst * COUT + o, av);
        }
    };

    // invariant before A: vA ~ e, vB ~ e+S, xpA = x(vA)
    float4 vA = g_e4[e];
    float4 vB = g_e4[e + STEP];             // pad-safe
    ull xpA[P], xpB[P];
    edge_loadx<CIN>(xpA, xin, vA.x);

    while (true) {
        // A: consume (vA, xpA)
        edge_loadx<CIN>(xpB, xin, vB.x);
        compute(vA, xpA);
        vA = g_e4[e + 2 * STEP];            // pad-safe; vA ~ e+2S
        e += STEP;
        if (e >= e1) break;
        // B: consume (vB, xpB); vA ~ e+S now
        edge_loadx<CIN>(xpA, xin, vA.x);
        compute(vB, xpB);
        vB = g_e4[e + 2 * STEP];            // pad-safe; vB ~ e+2S
        e += STEP;
        if (e >= e1) break;
    }
}

extern "C" void kernel_launch(void* const* d_in, const int* in_sizes, int n_in,
                              void* d_out, int out_size) {
    const float* x  = (const float*)d_in[0];
    const int*   ei = (const int*)d_in[1];
    const float* ea = (const float*)d_in[2];
    const float *W[5], *R[5], *B[5];
    for (int l = 0; l < 5; l++) {
        W[l] = (const float*)d_in[3 + 3 * l];
        R[l] = (const float*)d_in[4 + 3 * l];
        B[l] = (const float*)d_in[5 + 3 * l];
    }
    float* out = (float*)d_out;

    float *h0, *h1, *accA, *accB;
    cudaGetSymbolAddress((void**)&h0, g_h0);
    cudaGetSymbolAddress((void**)&h1, g_h1);
    cudaGetSymbolAddress((void**)&accA, g_accA);
    cudaGetSymbolAddress((void**)&accB, g_accB);

    // edge preprocessing: hierarchical counting sort by B-spline cell
    k_hist<<<NB, 256>>>(ea);
    k_cellscan<<<NCELL, NB>>>();
    k_scan<<<1, 64>>>();
    k_scatter<<<NB, 256>>>(ea, ei);

    const int EG = NCELL * CHUNKS;

    // L1: h0(N,1) -> accA(N,8)
    k_first<<<(NN * 8 + 255) / 256, 256>>>(x, R[0], B[0], h0, accA);
    k_edge1<<<EG, EBLK>>>(h0, W[0], accA);
    // boundary: h1 = elu(accA)(N,8); accB = init L2 (N,16)
    k_act<8, 16><<<NN / 16, 256>>>(accA, h1, R[1], B[1], accB);
    k_edgeP<8, 16><<<EG, EBLK>>>(h1, W[1], accB);
    // boundary: h0 = elu(accB)(N,16); accA = init L3 (N,16)
    k_act<16, 16><<<NN / 16, 256>>>(accB, h0, R[2], B[2], accA);
    k_edgeP<16, 16><<<EG, EBLK>>>(h0, W[2], accA);
    // boundary: h1 = elu(accA)(N,16); accB = init L4 (N,8)
    k_act<16, 8><<<NN / 16, 256>>>(accA, h1, R[3], B[3], accB);
    k_edgeP<16, 8><<<EG, EBLK>>>(h1, W[3], accB);
    // boundary: h0 = elu(accB)(N,8); accA = init L5 (N,1)
    k_act<8, 1><<<NN / 16, 256>>>(accB, h0, R[4], B[4], accA);
    k_edgeP<8, 1><<<EG, EBLK>>>(h0, W[4], accA);
    // final ELU
    k_elu<<<(NN + 255) / 256, 256>>>(accA, out, NN);
}

// round 15
// speedup vs baseline: 1.1311x; 1.1311x over previous
#include <cuda_runtime.h>
#include <math.h>

#define NN 50000
#define NE 400000
#define NCELL 64
#define NB 512
#define EPB_S ((NE + NB - 1) / NB)
#define CHUNKS 50
#define EBLK 128
#define EPAD 1024

typedef unsigned long long ull;

// ---- persistent scratch (no allocations allowed) ----
__device__ float  g_h0[NN * 16];
__device__ float  g_h1[NN * 16];
__device__ float  g_accA[NN * 16];
__device__ float  g_accB[NN * 16];
__device__ int    g_hist[NCELL];
__device__ int    g_segs[NCELL + 1];
__device__ int    g_bcount[NCELL * NB];
// zero-initialized; pad tail [NE, NE+EPAD) is never written -> stays zero across
// replays, making unguarded prefetch loads safe (srcdst=0 -> reads h[0]).
__device__ float4 g_e4[NE + EPAD];   // {srcdst packed 16/16 (bitcast), fx, fy, fz}

// ---- f32x2 packed-math helpers ----
__device__ __forceinline__ ull pack2(float lo, float hi) {
    ull r;
    asm("mov.b64 %0, {%1, %2};" : "=l"(r) : "f"(lo), "f"(hi));
    return r;
}
__device__ __forceinline__ void unpack2(ull v, float& lo, float& hi) {
    asm("mov.b64 {%0, %1}, %2;" : "=f"(lo), "=f"(hi) : "l"(v));
}
__device__ __forceinline__ void ffma2(ull& d, ull a, ull b) {
    asm("fma.rn.f32x2 %0, %1, %2, %0;" : "+l"(d) : "l"(a), "l"(b));
}
__device__ __forceinline__ ull add2(ull a, ull b) {
    ull r;
    asm("add.rn.f32x2 %0, %1, %2;" : "=l"(r) : "l"(a), "l"(b));
    return r;
}

__device__ __forceinline__ void cell_frac(float a, int& k0, float& fr) {
    float p = fminf(fmaxf(a, 0.f), 1.f) * 4.f;   // KSIZE-1 = 4
    int k = (int)floorf(p);
    k = k > 3 ? 3 : k;
    k0 = k;
    fr = p - (float)k;
}

// ---- pass 1: per-block cell histogram ----
__global__ __launch_bounds__(256)
void k_hist(const float* __restrict__ ea) {
    __shared__ int sh[NCELL];
    if (threadIdx.x < NCELL) sh[threadIdx.x] = 0;
    __syncthreads();
    int b = blockIdx.x;
    int e0 = b * EPB_S, e1 = min(NE, e0 + EPB_S);
    for (int e = e0 + threadIdx.x; e < e1; e += 256) {
        int kx, ky, kz; float f;
        cell_frac(ea[e * 3 + 0], kx, f);
        cell_frac(ea[e * 3 + 1], ky, f);
        cell_frac(ea[e * 3 + 2], kz, f);
        atomicAdd(&sh[kx * 16 + ky * 4 + kz], 1);
    }
    __syncthreads();
    if (threadIdx.x < NCELL) g_bcount[threadIdx.x * NB + b] = sh[threadIdx.x];
}

// ---- pass 2: per-cell exclusive scan over blocks; totals -> g_hist ----
__global__ __launch_bounds__(NB)
void k_cellscan() {
    __shared__ int sh[NB];
    int c = blockIdx.x, t = threadIdx.x;
    int v = g_bcount[c * NB + t];
    sh[t] = v;
    __syncthreads();
    for (int off = 1; off < NB; off <<= 1) {
        int val = (t >= off) ? sh[t - off] : 0;
        __syncthreads();
        sh[t] += val;
        __syncthreads();
    }
    g_bcount[c * NB + t] = sh[t] - v;
    if (t == NB - 1) g_hist[c] = sh[t];
}

// ---- pass 3: scatter; per-block local segs from g_hist (k_scan folded in) ----
__global__ __launch_bounds__(256)
void k_scatter(const float* __restrict__ ea, const int* __restrict__ ei) {
    __shared__ int hsh[NCELL];
    __shared__ int base[NCELL + 1];
    __shared__ int cur[NCELL];
    int b = blockIdx.x;
    if (threadIdx.x < NCELL) hsh[threadIdx.x] = g_hist[threadIdx.x];
    __syncthreads();
    if (threadIdx.x == 0) {
        int s = 0;
#pragma unroll
        for (int c = 0; c < NCELL; c++) { base[c] = s; s += hsh[c]; }
        base[NCELL] = s;
    }
    __syncthreads();
    if (threadIdx.x < NCELL)
        cur[threadIdx.x] = base[threadIdx.x] + g_bcount[threadIdx.x * NB + b];
    // block 0 publishes g_segs for the edge kernels (stream-ordered; idempotent)
    if (b == 0 && threadIdx.x <= NCELL) g_segs[threadIdx.x] = base[threadIdx.x];
    __syncthreads();
    int e0 = b * EPB_S, e1 = min(NE, e0 + EPB_S);
    for (int e = e0 + threadIdx.x; e < e1; e += 256) {
        int kx, ky, kz; float fx, fy, fz;
        cell_frac(ea[e * 3 + 0], kx, fx);
        cell_frac(ea[e * 3 + 1], ky, fy);
        cell_frac(ea[e * 3 + 2], kz, fz);
        int cell = kx * 16 + ky * 4 + kz;
        int pos = atomicAdd(&cur[cell], 1);
        unsigned int sd = (unsigned int)ei[e] | ((unsigned int)ei[NE + e] << 16);
        float4 v;
        v.x = __uint_as_float(sd);
        v.y = fx; v.z = fy; v.w = fz;
        g_e4[pos] = v;
    }
}

// ---- first layer prologue ----
__global__ void k_first(const float* __restrict__ x, const float* __restrict__ root,
                        const float* __restrict__ bias, float* __restrict__ h,
                        float* __restrict__ acc) {
    int idx = blockIdx.x * blockDim.x + threadIdx.x;
    if (idx >= NN * 8) return;
    int n = idx >> 3, o = idx & 7;
    const float L = -0.22703196f, U = 0.36853024f;
    float t = (x[n] - L) / (U - L) * 20.f - 10.f;
    t = fminf(fmaxf(t, -10.f), 10.f);
    if (o == 0) h[n] = t;
    acc[idx] = bias[o] + t * root[o];
}

// ---- fused layer boundary: h = elu(accin); accout = bias + h @ root ----
template <int CIN, int COUT>
__global__ __launch_bounds__(256)
void k_act(const float* __restrict__ accin, float* __restrict__ hout,
           const float* __restrict__ root, const float* __restrict__ bias,
           float* __restrict__ accout) {
    __shared__ float sh[16 * CIN];
    __shared__ float sr[CIN * COUT];
    int t = threadIdx.x;
    int n0 = blockIdx.x * 16;
    if (t < CIN * COUT) sr[t] = root[t];
    if (t < 16 * CIN) {
        int n = n0 + t / CIN;
        float v = accin[n * CIN + (t % CIN)];
        v = v > 0.f ? v : expm1f(v);
        sh[t] = v;
        hout[n * CIN + (t % CIN)] = v;
    }
    __syncthreads();
    if (t < 16 * COUT) {
        int nl = t / COUT, o = t % COUT;
        float s = bias[o];
#pragma unroll
        for (int i = 0; i < CIN; i++) s += sh[nl * CIN + i] * sr[i * COUT + o];
        accout[(n0 + nl) * COUT + o] = s;
    }
}

__global__ void k_elu(const float* __restrict__ a, float* __restrict__ o, int n) {
    int i = blockIdx.x * blockDim.x + threadIdx.x;
    if (i < n) {
        float v = a[i];
        o[i] = v > 0.f ? v : expm1f(v);
    }
}

// ---- edge kernel, CIN==1 (layer 1): depth-2 pipeline, unguarded pad prefetch ----
__global__ __launch_bounds__(EBLK)
void k_edge1(const float* __restrict__ xin, const float* __restrict__ w,
             float* __restrict__ acc) {
    constexpr int COUT = 8, G = 16, EPB = EBLK / G;
    constexpr int STEP = CHUNKS * EPB;
    int cell = blockIdx.x / CHUNKS;
    int chunk = blockIdx.x % CHUNKS;
    int tid = threadIdx.x;
    int g = tid % G;
    int o = g % COUT;
    int h = g / COUT;
    int eslot = tid / G;
    int lane = tid & 31;
    unsigned gmask = ((1u << G) - 1u) << ((lane / G) * G);

    int cx = cell >> 4, cy = (cell >> 2) & 3, cz = cell & 3;
    float wr[4];
#pragma unroll
    for (int sl = 0; sl < 4; sl++) {
        int bx = sl & 1, by = (sl >> 1) & 1;
        int k = (cx + bx) * 25 + (cy + by) * 5 + (cz + h);
        wr[sl] = w[k * COUT + o];
    }

    int e1 = g_segs[cell + 1];
    int e = g_segs[cell] + chunk * EPB + eslot;
    if (e >= e1) return;

    float4 v0 = g_e4[e];
    float4 v1 = g_e4[e + STEP];             // pad-safe
    float x0 = xin[__float_as_int(v0.x) & 0xffff];

    for (; e < e1; e += STEP) {
        float4 v2 = g_e4[e + 2 * STEP];     // pad-safe
        float x1 = xin[__float_as_int(v1.x) & 0xffff];

        float fx = v0.y, fy = v0.z, fz = v0.w;
        float wz = h ? fz : (1.f - fz);
        float gx = 1.f - fx, gy = 1.f - fy;
        float s = (gx * gy) * wr[0] + (fx * gy) * wr[1]
                + (gx * fy) * wr[2] + (fx * fy) * wr[3];
        float av = x0 * (s * wz);
        av += __shfl_xor_sync(gmask, av, COUT);
        float hi2 = __shfl_xor_sync(gmask, av, 1);
        unsigned dst = ((unsigned)__float_as_int(v0.x)) >> 16;
        if (h == 0 && (o & 1) == 0)
            asm volatile("red.global.add.v2.f32 [%0], {%1, %2};"
                         :: "l"(acc + dst * COUT + o), "f"(av), "f"(hi2) : "memory");
        v0 = v1; x0 = x1;
        v1 = v2;
    }
}

// ---- edge kernel, packed f32x2, depth-2, unguarded pad prefetch (CIN {8,16}) ----
template <int CIN, int COUT>
__global__ __launch_bounds__(EBLK)
void k_edgeP(const float* __restrict__ xin, const float* __restrict__ w,
             float* __restrict__ acc) {
    constexpr int G = 2 * COUT;
    constexpr int EPB = EBLK / G;
    constexpr int STEP = CHUNKS * EPB;
    constexpr int P = CIN / 2;
    int cell = blockIdx.x / CHUNKS;
    int chunk = blockIdx.x % CHUNKS;
    int tid = threadIdx.x;
    int g = tid % G;
    int o = g % COUT;
    int h = g / COUT;
    int eslot = tid / G;
    int lane = tid & 31;
    unsigned gmask = (G >= 32) ? 0xffffffffu : (((1u << G) - 1u) << ((lane / G) * G));

    int cx = cell >> 4, cy = (cell >> 2) & 3, cz = cell & 3;

    ull wp[4][P];
#pragma unroll
    for (int sl = 0; sl < 4; sl++) {
        int bx = sl & 1, by = (sl >> 1) & 1;
        int k = (cx + bx) * 25 + (cy + by) * 5 + (cz + h);
#pragma unroll
        for (int i = 0; i < P; i++)
            wp[sl][i] = pack2(w[(k * CIN + 2 * i) * COUT + o],
                              w[(k * CIN + 2 * i + 1) * COUT + o]);
    }

    int e1 = g_segs[cell + 1];
    int e = g_segs[cell] + chunk * EPB + eslot;
    if (e >= e1) return;

    float4 v0 = g_e4[e];
    float4 v1 = g_e4[e + STEP];             // pad-safe
    ull xp[P];
    {
        const longlong2* xv = reinterpret_cast<const longlong2*>(
            xin + (__float_as_int(v0.x) & 0xffff) * CIN);
#pragma unroll
        for (int i = 0; i < P / 2; i++) {
            longlong2 q = xv[i];
            xp[2 * i] = (ull)q.x;
            xp[2 * i + 1] = (ull)q.y;
        }
    }

    for (; e < e1; e += STEP) {
        float4 v2 = g_e4[e + 2 * STEP];     // pad-safe
        ull xpn[P];
        {
            const longlong2* xv = reinterpret_cast<const longlong2*>(
                xin + (__float_as_int(v1.x) & 0xffff) * CIN);
#pragma unroll
            for (int i = 0; i < P / 2; i++) {
                longlong2 q = xv[i];
                xpn[2 * i] = (ull)q.x;
                xpn[2 * i + 1] = (ull)q.y;
            }
        }

        float fx = v0.y, fy = v0.z, fz = v0.w;
        float wz = h ? fz : (1.f - fz);
        float gx = 1.f - fx, gy = 1.f - fy;
        float bas[4];
        bas[0] = gx * gy * wz; bas[1] = fx * gy * wz;
        bas[2] = gx * fy * wz; bas[3] = fx * fy * wz;

        ull av2 = 0;
#pragma unroll
        for (int sl = 0; sl < 4; sl++) {
            ull t0 = 0, t1 = 0;
#pragma unroll
            for (int i = 0; i + 1 < P; i += 2) {
                ffma2(t0, xp[i], wp[sl][i]);
                ffma2(t1, xp[i + 1], wp[sl][i + 1]);
            }
            if constexpr (P & 1) ffma2(t0, xp[P - 1], wp[sl][P - 1]);
            ffma2(av2, pack2(bas[sl], bas[sl]), add2(t0, t1));
        }
        float alo, ahi;
        unpack2(av2, alo, ahi);
        float av = alo + ahi;

        av += __shfl_xor_sync(gmask, av, COUT);   // combine z-corner halves
        unsigned dst = ((unsigned)__float_as_int(v0.x)) >> 16;
        if constexpr (COUT >= 8) {
            float hi2 = __shfl_xor_sync(gmask, av, 1);
            if (h == 0 && (o & 1) == 0)
                asm volatile("red.global.add.v2.f32 [%0], {%1, %2};"
                             :: "l"(acc + dst * COUT + o), "f"(av), "f"(hi2) : "memory");
        } else {
            if (h == 0) atomicAdd(acc + dst * COUT + o, av);
        }

        v0 = v1;
#pragma unroll
        for (int i = 0; i < P; i++) xp[i] = xpn[i];
        v1 = v2;
    }
}

extern "C" void kernel_launch(void* const* d_in, const int* in_sizes, int n_in,
                              void* d_out, int out_size) {
    const float* x  = (const float*)d_in[0];
    const int*   ei = (const int*)d_in[1];
    const float* ea = (const float*)d_in[2];
    const float *W[5], *R[5], *B[5];
    for (int l = 0; l < 5; l++) {
        W[l] = (const float*)d_in[3 + 3 * l];
        R[l] = (const float*)d_in[4 + 3 * l];
        B[l] = (const float*)d_in[5 + 3 * l];
    }
    float* out = (float*)d_out;

    float *h0, *h1, *accA, *accB;
    cudaGetSymbolAddress((void**)&h0, g_h0);
    cudaGetSymbolAddress((void**)&h1, g_h1);
    cudaGetSymbolAddress((void**)&accA, g_accA);
    cudaGetSymbolAddress((void**)&accB, g_accB);

    // edge preprocessing: hierarchical counting sort by B-spline cell
    k_hist<<<NB, 256>>>(ea);
    k_cellscan<<<NCELL, NB>>>();
    k_scatter<<<NB, 256>>>(ea, ei);

    const int EG = NCELL * CHUNKS;

    // L1: h0(N,1) -> accA(N,8)
    k_first<<<(NN * 8 + 255) / 256, 256>>>(x, R[0], B[0], h0, accA);
    k_edge1<<<EG, EBLK>>>(h0, W[0], accA);
    // boundary: h1 = elu(accA)(N,8); accB = init L2 (N,16)
    k_act<8, 16><<<NN / 16, 256>>>(accA, h1, R[1], B[1], accB);
    k_edgeP<8, 16><<<EG, EBLK>>>(h1, W[1], accB);
    // boundary: h0 = elu(accB)(N,16); accA = init L3 (N,16)
    k_act<16, 16><<<NN / 16, 256>>>(accB, h0, R[2], B[2], accA);
    k_edgeP<16, 16><<<EG, EBLK>>>(h0, W[2], accA);
    // boundary: h1 = elu(accA)(N,16); accB = init L4 (N,8)
    k_act<16, 8><<<NN / 16, 256>>>(accA, h1, R[3], B[3], accB);
    k_edgeP<16, 8><<<EG, EBLK>>>(h1, W[3], accB);
    // boundary: h0 = elu(accB)(N,8); accA = init L5 (N,1)
    k_act<8, 1><<<NN / 16, 256>>>(accB, h0, R[4], B[4], accA);
    k_edgeP<8, 1><<<EG, EBLK>>>(h0, W[4], accA);
    // final ELU
    k_elu<<<(NN + 255) / 256, 256>>>(accA, out, NN);
}